// round 3
// baseline (speedup 1.0000x reference)
#include <cuda_runtime.h>
#include <math.h>
#include <stdint.h>

// Problem constants
#define B_ 256
#define L_ 512
#define H_ 1024
#define S_ 16
#define HOR_ 64
#define PRED_ELEMS (B_*HOR_*L_)   // 8388608

// ---------------- scratch (device globals; no allocation allowed) ----------
__device__ float g_q[B_*H_];
__device__ float g_kmem[S_*H_];
__device__ float g_vmem[S_*H_];
__device__ float g_ctx[B_*H_];
__device__ float g_context[B_*L_];
__device__ float g_pgh[B_*H_];
__device__ float g_prior[B_*L_];
__device__ float g_gates[B_*4*H_];
__device__ float g_t[B_*H_];
__device__ float g_h0[B_*H_];
__device__ float g_c0[B_*H_];
__device__ float g_h1[B_*H_];
__device__ float g_c1[B_*H_];

// ---------------- dual-source GEMM ------------------------------------------
// C[M,N] = act( A1[M,K1] @ W1[N,K1]^T + A2[M,K2] @ W2[N,K2]^T + b1 + b2 )
// A row stride = lda, W row stride = ldw, C row stride = ldc.
template<int BM,int BN,int BK,int TM,int TN,int NT>
__global__ __launch_bounds__(NT)
void gemm2_kernel(const float* __restrict__ A1, int lda1,
                  const float* __restrict__ W1, int ldw1, int K1,
                  const float* __restrict__ A2, int lda2,
                  const float* __restrict__ W2, int ldw2, int K2,
                  const float* __restrict__ b1, const float* __restrict__ b2,
                  float* __restrict__ C, int ldc, int M, int N, int relu)
{
    __shared__ __align__(16) float As[BK][BM+4];
    __shared__ __align__(16) float Ws[BK][BN+4];

    const int tid = threadIdx.x;
    const int m0  = blockIdx.y * BM;
    const int n0  = blockIdx.x * BN;
    const int m0t = (tid / (BN/TN)) * TM;
    const int n0t = (tid % (BN/TN)) * TN;

    float acc[TM][TN];
    #pragma unroll
    for (int i = 0; i < TM; i++)
        #pragma unroll
        for (int j = 0; j < TN; j++) acc[i][j] = 0.f;

    for (int src = 0; src < 2; src++) {
        const float* A = src ? A2 : A1;
        if (A == nullptr) break;
        const float* W = src ? W2 : W1;
        const int lda  = src ? lda2 : lda1;
        const int ldw  = src ? ldw2 : ldw1;
        const int K    = src ? K2   : K1;

        for (int k0 = 0; k0 < K; k0 += BK) {
            // --- load A tile (BM x BK), store transposed into As[k][m] ---
            constexpr int A4 = BM*BK/4;
            #pragma unroll
            for (int it = 0; it < A4/NT; it++) {
                int i4  = tid + NT*it;
                int row = i4 / (BK/4);
                int cv  = i4 % (BK/4);
                float4 val = make_float4(0.f,0.f,0.f,0.f);
                int gr = m0 + row;
                if (gr < M)
                    val = *reinterpret_cast<const float4*>(A + (size_t)gr*lda + k0 + cv*4);
                As[cv*4+0][row] = val.x;
                As[cv*4+1][row] = val.y;
                As[cv*4+2][row] = val.z;
                As[cv*4+3][row] = val.w;
            }
            // --- load W tile (BN x BK), store transposed into Ws[k][n] ---
            constexpr int W4 = BN*BK/4;
            #pragma unroll
            for (int it = 0; it < W4/NT; it++) {
                int i4  = tid + NT*it;
                int row = i4 / (BK/4);
                int cv  = i4 % (BK/4);
                float4 val = *reinterpret_cast<const float4*>(W + (size_t)(n0+row)*ldw + k0 + cv*4);
                Ws[cv*4+0][row] = val.x;
                Ws[cv*4+1][row] = val.y;
                Ws[cv*4+2][row] = val.z;
                Ws[cv*4+3][row] = val.w;
            }
            __syncthreads();

            #pragma unroll
            for (int kk = 0; kk < BK; kk++) {
                float a[TM], bb[TN];
                #pragma unroll
                for (int i = 0; i < TM; i += 4) {
                    float4 t = *reinterpret_cast<const float4*>(&As[kk][m0t + i]);
                    a[i]=t.x; a[i+1]=t.y; a[i+2]=t.z; a[i+3]=t.w;
                }
                #pragma unroll
                for (int j = 0; j < TN; j += 4) {
                    float4 t = *reinterpret_cast<const float4*>(&Ws[kk][n0t + j]);
                    bb[j]=t.x; bb[j+1]=t.y; bb[j+2]=t.z; bb[j+3]=t.w;
                }
                #pragma unroll
                for (int i = 0; i < TM; i++)
                    #pragma unroll
                    for (int j = 0; j < TN; j++)
                        acc[i][j] = fmaf(a[i], bb[j], acc[i][j]);
            }
            __syncthreads();
        }
    }

    // --- epilogue ---
    #pragma unroll
    for (int j = 0; j < TN; j++) {
        int gn = n0 + n0t + j;
        float bias = (b1 ? b1[gn] : 0.f) + (b2 ? b2[gn] : 0.f);
        #pragma unroll
        for (int i = 0; i < TM; i++) {
            int gm = m0 + m0t + i;
            if (gm < M) {
                float vo = acc[i][j] + bias;
                if (relu) vo = fmaxf(vo, 0.f);
                C[(size_t)gm*ldc + gn] = vo;
            }
        }
    }
}

// ---------------- attention (scores -> softmax -> ctx) ----------------------
// one block per batch row; 16 slots, dim 1024
__global__ __launch_bounds__(256)
void attn_kernel(const float* __restrict__ q, const float* __restrict__ k,
                 const float* __restrict__ v, float* __restrict__ ctx)
{
    const int b   = blockIdx.x;
    const int tid = threadIdx.x;
    const int lane = tid & 31, wid = tid >> 5;

    float p[S_];
    #pragma unroll
    for (int s = 0; s < S_; s++) p[s] = 0.f;

    for (int e = tid; e < H_; e += 256) {
        float qv = q[b*H_ + e];
        #pragma unroll
        for (int s = 0; s < S_; s++)
            p[s] = fmaf(qv, k[s*H_ + e], p[s]);
    }
    // warp reduce
    #pragma unroll
    for (int s = 0; s < S_; s++) {
        #pragma unroll
        for (int off = 16; off > 0; off >>= 1)
            p[s] += __shfl_down_sync(0xffffffffu, p[s], off);
    }
    __shared__ float sred[S_ * 8];
    __shared__ float wts[S_];
    if (lane == 0) {
        #pragma unroll
        for (int s = 0; s < S_; s++) sred[s*8 + wid] = p[s];
    }
    __syncthreads();
    if (tid == 0) {
        float sc[S_];
        float mx = -1e30f;
        #pragma unroll
        for (int s = 0; s < S_; s++) {
            float acc = 0.f;
            #pragma unroll
            for (int w = 0; w < 8; w++) acc += sred[s*8 + w];
            sc[s] = acc * (1.0f/32.0f);   // / sqrt(1024)
            mx = fmaxf(mx, sc[s]);
        }
        float sum = 0.f;
        #pragma unroll
        for (int s = 0; s < S_; s++) { sc[s] = expf(sc[s] - mx); sum += sc[s]; }
        float inv = 1.f / sum;
        #pragma unroll
        for (int s = 0; s < S_; s++) wts[s] = sc[s] * inv;
    }
    __syncthreads();

    for (int j = tid; j < H_; j += 256) {
        float acc = 0.f;
        #pragma unroll
        for (int s = 0; s < S_; s++)
            acc = fmaf(wts[s], v[s*H_ + j], acc);
        ctx[b*H_ + j] = acc;
    }
}

// ---------------- pointwise LSTM cell ---------------------------------------
__global__ __launch_bounds__(256)
void lstm_cell_kernel(const float* __restrict__ gates,
                      const float* __restrict__ c_in,
                      float* __restrict__ h_out, float* __restrict__ c_out)
{
    int idx = blockIdx.x*blockDim.x + threadIdx.x;   // 0 .. B*H-1
    if (idx >= B_*H_) return;
    int b = idx >> 10;
    int j = idx & (H_-1);
    const float* g = gates + (size_t)b*4*H_ + j;
    float gi = g[0], gf = g[H_], gg = g[2*H_], go = g[3*H_];
    float i  = 1.f / (1.f + expf(-gi));
    float f  = 1.f / (1.f + expf(-gf));
    float gt = tanhf(gg);
    float o  = 1.f / (1.f + expf(-go));
    float c  = f * c_in[idx] + i * gt;
    h_out[idx] = o * tanhf(c);
    c_out[idx] = c;
}

// ---------------- zero LSTM state -------------------------------------------
__global__ __launch_bounds__(256)
void zero_state_kernel()
{
    int i = blockIdx.x*blockDim.x + threadIdx.x;
    if (i < B_*H_) { g_h0[i]=0.f; g_c0[i]=0.f; g_h1[i]=0.f; g_c1[i]=0.f; }
}

// ---------------- host-side launch helpers ----------------------------------
static inline void gemm_big(const float* A1,int lda1,const float* W1,int ldw1,int K1,
                            const float* A2,int lda2,const float* W2,int ldw2,int K2,
                            const float* b1,const float* b2,
                            float* C,int ldc,int M,int N,int relu)
{
    dim3 grid(N/64, (M + 127)/128);
    gemm2_kernel<128,64,16,8,4,256><<<grid,256>>>(A1,lda1,W1,ldw1,K1,
                                                  A2,lda2,W2,ldw2,K2,
                                                  b1,b2,C,ldc,M,N,relu);
}
static inline void gemm_small(const float* A1,int lda1,const float* W1,int ldw1,int K1,
                              const float* A2,int lda2,const float* W2,int ldw2,int K2,
                              const float* b1,const float* b2,
                              float* C,int ldc,int M,int N,int relu)
{
    dim3 grid(N/32, (M + 63)/64);
    gemm2_kernel<64,32,16,4,4,128><<<grid,128>>>(A1,lda1,W1,ldw1,K1,
                                                 A2,lda2,W2,ldw2,K2,
                                                 b1,b2,C,ldc,M,N,relu);
}

extern "C" void kernel_launch(void* const* d_in, const int* in_sizes, int n_in,
                              void* d_out, int out_size)
{
    (void)in_sizes; (void)n_in;
    // metadata order (setup_inputs dict order)
    const float* cs    = (const float*)d_in[0];
    // d_in[1] = horizon (int scalar) -- fixed at 64
    const float* mem   = (const float*)d_in[2];
    const float* qW    = (const float*)d_in[3];
    const float* qb    = (const float*)d_in[4];
    const float* kW    = (const float*)d_in[5];
    const float* kb    = (const float*)d_in[6];
    const float* vW    = (const float*)d_in[7];
    const float* vb    = (const float*)d_in[8];
    const float* moW   = (const float*)d_in[9];
    const float* mob   = (const float*)d_in[10];
    const float* pgW1  = (const float*)d_in[11];
    const float* pgb1  = (const float*)d_in[12];
    const float* pgW2  = (const float*)d_in[13];
    const float* pgb2  = (const float*)d_in[14];
    const float* wih0  = (const float*)d_in[15];
    const float* whh0  = (const float*)d_in[16];
    const float* bih0  = (const float*)d_in[17];
    const float* bhh0  = (const float*)d_in[18];
    const float* wih1  = (const float*)d_in[19];
    const float* whh1  = (const float*)d_in[20];
    const float* bih1  = (const float*)d_in[21];
    const float* bhh1  = (const float*)d_in[22];
    const float* opW1  = (const float*)d_in[23];
    const float* opb1  = (const float*)d_in[24];
    const float* opW2  = (const float*)d_in[25];
    const float* opb2  = (const float*)d_in[26];

    float* out = (float*)d_out;

    // scratch symbol addresses
    float *q, *km, *vm, *ctx, *cxt, *pgh, *prior_s, *gates, *tbuf, *h0, *c0, *h1, *c1;
    cudaGetSymbolAddress((void**)&q,     g_q);
    cudaGetSymbolAddress((void**)&km,    g_kmem);
    cudaGetSymbolAddress((void**)&vm,    g_vmem);
    cudaGetSymbolAddress((void**)&ctx,   g_ctx);
    cudaGetSymbolAddress((void**)&cxt,   g_context);
    cudaGetSymbolAddress((void**)&pgh,   g_pgh);
    cudaGetSymbolAddress((void**)&prior_s, g_prior);
    cudaGetSymbolAddress((void**)&gates, g_gates);
    cudaGetSymbolAddress((void**)&tbuf,  g_t);
    cudaGetSymbolAddress((void**)&h0,    g_h0);
    cudaGetSymbolAddress((void**)&c0,    g_c0);
    cudaGetSymbolAddress((void**)&h1,    g_h1);
    cudaGetSymbolAddress((void**)&c1,    g_c1);

    // prior goes straight into d_out's second output region when it exists
    bool has_prior_region = (out_size >= PRED_ELEMS + B_*L_);
    float* priorbuf = has_prior_region ? (out + PRED_ELEMS) : prior_s;

    // ---- init recurrent state ----
    zero_state_kernel<<<(B_*H_ + 255)/256, 256>>>();

    // ---- context memory read ----
    gemm_small(cs, L_,  qW, L_,  L_,  nullptr,0,nullptr,0,0, qb, nullptr, q,  H_, B_, H_, 0);
    gemm_small(mem,H_,  kW, H_,  H_,  nullptr,0,nullptr,0,0, kb, nullptr, km, H_, S_, H_, 0);
    gemm_small(mem,H_,  vW, H_,  H_,  nullptr,0,nullptr,0,0, vb, nullptr, vm, H_, S_, H_, 0);
    attn_kernel<<<B_, 256>>>(q, km, vm, ctx);
    gemm_small(ctx,H_,  moW,H_,  H_,  nullptr,0,nullptr,0,0, mob,nullptr, cxt,L_, B_, L_, 0);

    // ---- prior generator: relu(concat(state,context) @ pgW1^T + b1) @ pgW2^T + b2
    gemm_small(cs, L_,  pgW1,      2*L_, L_,
               cxt,L_,  pgW1 + L_, 2*L_, L_,
               pgb1, nullptr, pgh, H_, B_, H_, 1);
    gemm_small(pgh,H_,  pgW2,H_, H_, nullptr,0,nullptr,0,0, pgb2,nullptr,
               priorbuf, L_, B_, L_, 0);

    // ---- autoregressive rollout ----
    for (int s = 0; s < HOR_; s++) {
        const float* x = (s == 0) ? priorbuf : (out + (size_t)(s-1)*L_);
        int ldx        = (s == 0) ? L_ : HOR_*L_;

        // layer 0 gates: x @ wih0^T + h0 @ whh0^T + bih0 + bhh0
        gemm_big(x,  ldx, wih0, L_, L_,
                 h0, H_,  whh0, H_, H_,
                 bih0, bhh0, gates, 4*H_, B_, 4*H_, 0);
        lstm_cell_kernel<<<(B_*H_ + 255)/256, 256>>>(gates, c0, h0, c0);

        // layer 1 gates: h0 @ wih1^T + h1 @ whh1^T + bih1 + bhh1
        gemm_big(h0, H_, wih1, H_, H_,
                 h1, H_, whh1, H_, H_,
                 bih1, bhh1, gates, 4*H_, B_, 4*H_, 0);
        lstm_cell_kernel<<<(B_*H_ + 255)/256, 256>>>(gates, c1, h1, c1);

        // output proj: pred = relu(h1 @ opW1^T + b1) @ opW2^T + b2
        gemm_small(h1, H_, opW1, H_, H_, nullptr,0,nullptr,0,0, opb1,nullptr,
                   tbuf, H_, B_, H_, 1);
        gemm_small(tbuf,H_, opW2, H_, H_, nullptr,0,nullptr,0,0, opb2,nullptr,
                   out + (size_t)s*L_, HOR_*L_, B_, L_, 0);
    }
}

// round 5
// speedup vs baseline: 2.3618x; 2.3618x over previous
#include <cuda_runtime.h>
#include <cuda_bf16.h>
#include <math.h>
#include <stdint.h>

#define B_ 256
#define L_ 512
#define H_ 1024
#define S_ 16
#define HOR_ 64
#define PRED_ELEMS (B_*HOR_*L_)

typedef __nv_bfloat16 bf16;

// ---------------- fp32 scratch ----------------------------------------------
__device__ float g_q[B_*H_];
__device__ float g_kmem[S_*H_];
__device__ float g_vmem[S_*H_];
__device__ float g_ctx[B_*H_];
__device__ float g_context[B_*L_];
__device__ float g_pgh[B_*H_];
__device__ float g_prior[B_*L_];
__device__ float g_gates[B_*4*H_];
__device__ float g_c0[B_*H_];
__device__ float g_c1[B_*H_];

// ---------------- bf16 split scratch ----------------------------------------
__device__ __align__(16) bf16 g_xh[B_*L_],  g_xl[B_*L_];
__device__ __align__(16) bf16 g_h0h[B_*H_], g_h0l[B_*H_];
__device__ __align__(16) bf16 g_h1h[B_*H_], g_h1l[B_*H_];
__device__ __align__(16) bf16 g_th[B_*H_],  g_tl[B_*H_];
__device__ __align__(16) bf16 g_wih0h[4*H_*L_], g_wih0l[4*H_*L_];
__device__ __align__(16) bf16 g_whh0h[4*H_*H_], g_whh0l[4*H_*H_];
__device__ __align__(16) bf16 g_wih1h[4*H_*H_], g_wih1l[4*H_*H_];
__device__ __align__(16) bf16 g_whh1h[4*H_*H_], g_whh1l[4*H_*H_];
__device__ __align__(16) bf16 g_opW1h[H_*H_],   g_opW1l[H_*H_];
__device__ __align__(16) bf16 g_opW2h[L_*H_],   g_opW2l[L_*H_];

// ---------------- low-level helpers ------------------------------------------
__device__ __forceinline__ uint32_t smem_u32(const void* p) {
    uint32_t a;
    asm("{ .reg .u64 t; cvta.to.shared.u64 t, %1; cvt.u32.u64 %0, t; }" : "=r"(a) : "l"(p));
    return a;
}

#define CP_ASYNC16(d, s) \
    asm volatile("cp.async.cg.shared.global [%0], [%1], 16;" :: "r"(d), "l"(s))
#define CP_COMMIT()  asm volatile("cp.async.commit_group;" ::: "memory")

__device__ __forceinline__ void ldm_x4(uint32_t* r, uint32_t addr) {
    asm volatile("ldmatrix.sync.aligned.m8n8.x4.shared.b16 {%0,%1,%2,%3}, [%4];"
                 : "=r"(r[0]), "=r"(r[1]), "=r"(r[2]), "=r"(r[3]) : "r"(addr));
}

__device__ __forceinline__ void mma16816(float* d, const uint32_t* a, const uint32_t* b) {
    asm volatile(
        "mma.sync.aligned.m16n8k16.row.col.f32.bf16.bf16.f32 "
        "{%0,%1,%2,%3}, {%4,%5,%6,%7}, {%8,%9}, {%0,%1,%2,%3};"
        : "+f"(d[0]), "+f"(d[1]), "+f"(d[2]), "+f"(d[3])
        : "r"(a[0]), "r"(a[1]), "r"(a[2]), "r"(a[3]), "r"(b[0]), "r"(b[1]));
}

// ---------------- tensor-core GEMM (bf16x3 split, fp32 accum, mma.sync) ------
// C[M,N] = act( A1@W1^T + A2@W2^T + b1 + b2 )
// A split (Ah,Al) [M,K] K-major; W split (Wh,Wl) [N,K] K-major.
// CTA tile 128x64, BK=32, 8 warps (warp tile 32x32), 2-stage cp.async pipeline.
#define STRIDE 40                 // smem row stride in bf16 elems (80 B)
#define AH_OFF 0
#define AL_OFF (128*STRIDE)       // 5120
#define WH_OFF (2*128*STRIDE)     // 10240
#define WL_OFF (WH_OFF + 64*STRIDE)
#define STAGE_ELEMS (WL_OFF + 64*STRIDE)   // 15360
#define STAGE_BYTES (STAGE_ELEMS*2)        // 30720
#define MMA_SMEM (2*STAGE_BYTES)           // 61440

__global__ __launch_bounds__(256)
void gemm_mma(const bf16* __restrict__ Ah1, const bf16* __restrict__ Al1,
              const bf16* __restrict__ Wh1, const bf16* __restrict__ Wl1, int K1,
              const bf16* __restrict__ Ah2, const bf16* __restrict__ Al2,
              const bf16* __restrict__ Wh2, const bf16* __restrict__ Wl2, int K2,
              const float* __restrict__ b1, const float* __restrict__ b2,
              float* __restrict__ C, int ldc,
              bf16* __restrict__ Oh, bf16* __restrict__ Ol, int ldo, int relu)
{
    extern __shared__ __align__(16) char smem[];
    const uint32_t sb = smem_u32(smem);
    const int tid    = threadIdx.x;
    const int lane   = tid & 31;
    const int wid    = tid >> 5;
    const int warp_m = wid >> 1;          // 0..3
    const int warp_n = wid & 1;           // 0..1
    const int m0     = blockIdx.y * 128;
    const int n0     = blockIdx.x * 64;

    const int nc1 = K1 >> 5;
    const int nc2 = (Ah2 != nullptr) ? (K2 >> 5) : 0;
    const int nc  = nc1 + nc2;

    float acc[2][4][4];
    #pragma unroll
    for (int i = 0; i < 2; i++)
        #pragma unroll
        for (int j = 0; j < 4; j++)
            #pragma unroll
            for (int r = 0; r < 4; r++) acc[i][j][r] = 0.f;

    // ---- chunk loader: fill stage (c&1) with 32 K-columns of Ah/Al/Wh/Wl ----
    auto do_load = [&](int c) {
        const int  src = (c < nc1) ? 0 : 1;
        const int  k0  = ((src == 0) ? c : (c - nc1)) << 5;
        const int  K   = (src == 0) ? K1 : K2;
        const bf16* Ah = (src == 0) ? Ah1 : Ah2;
        const bf16* Al = (src == 0) ? Al1 : Al2;
        const bf16* Wh = (src == 0) ? Wh1 : Wh2;
        const bf16* Wl = (src == 0) ? Wl1 : Wl2;
        const uint32_t st = sb + (uint32_t)(c & 1) * STAGE_BYTES;

        #pragma unroll
        for (int it = 0; it < 2; it++) {          // A: 128 rows x 4 16B-chunks
            int idx = tid + (it << 8);
            int row = idx >> 2, ch = idx & 3;
            uint32_t doff = (uint32_t)(row * STRIDE + ch * 8) * 2u;
            const bf16* ga = Ah + (size_t)(m0 + row) * K + k0 + ch * 8;
            const bf16* gl = Al + (size_t)(m0 + row) * K + k0 + ch * 8;
            CP_ASYNC16(st + AH_OFF*2 + doff, ga);
            CP_ASYNC16(st + AL_OFF*2 + doff, gl);
        }
        {                                          // W: 64 rows x 4 chunks
            int row = tid >> 2, ch = tid & 3;
            uint32_t doff = (uint32_t)(row * STRIDE + ch * 8) * 2u;
            const bf16* gh = Wh + (size_t)(n0 + row) * K + k0 + ch * 8;
            const bf16* gl = Wl + (size_t)(n0 + row) * K + k0 + ch * 8;
            CP_ASYNC16(st + WH_OFF*2 + doff, gh);
            CP_ASYNC16(st + WL_OFF*2 + doff, gl);
        }
        CP_COMMIT();
    };

    do_load(0);

    // per-warp ldmatrix lane address components
    const int a_row = warp_m * 32 + (lane & 15);          // + mi*16
    const int a_kof = (lane >> 4) << 3;                   // + k16*16
    const int b_row = warp_n * 32 + ((lane >> 4) << 3) + (lane & 7);  // + g*16
    const int b_kof = ((lane >> 3) & 1) << 3;

    for (int c = 0; c < nc; c++) {
        if (c + 1 < nc) {
            do_load(c + 1);
            asm volatile("cp.async.wait_group 1;" ::: "memory");
        } else {
            asm volatile("cp.async.wait_group 0;" ::: "memory");
        }
        __syncthreads();

        const uint32_t st = sb + (uint32_t)(c & 1) * STAGE_BYTES;

        #pragma unroll
        for (int k16 = 0; k16 < 2; k16++) {
            const int kk = k16 * 16;
            uint32_t ah[2][4], al[2][4], bh[2][4], bl[2][4];
            #pragma unroll
            for (int mi = 0; mi < 2; mi++) {
                uint32_t ra = st + (uint32_t)((AH_OFF + (a_row + mi*16) * STRIDE + kk + a_kof) * 2);
                ldm_x4(ah[mi], ra);
                uint32_t rl = st + (uint32_t)((AL_OFF + (a_row + mi*16) * STRIDE + kk + a_kof) * 2);
                ldm_x4(al[mi], rl);
            }
            #pragma unroll
            for (int g = 0; g < 2; g++) {
                uint32_t rb = st + (uint32_t)((WH_OFF + (b_row + g*16) * STRIDE + kk + b_kof) * 2);
                ldm_x4(bh[g], rb);
                uint32_t rc = st + (uint32_t)((WL_OFF + (b_row + g*16) * STRIDE + kk + b_kof) * 2);
                ldm_x4(bl[g], rc);
            }
            #pragma unroll
            for (int mi = 0; mi < 2; mi++)
                #pragma unroll
                for (int nj = 0; nj < 4; nj++) {
                    const int g = nj >> 1, o = (nj & 1) * 2;
                    mma16816(acc[mi][nj], ah[mi], &bh[g][o]);
                    mma16816(acc[mi][nj], al[mi], &bh[g][o]);
                    mma16816(acc[mi][nj], ah[mi], &bl[g][o]);
                }
        }
        __syncthreads();
    }

    // ---------------- epilogue ----------------
    const int m_base = m0 + warp_m * 32;
    const int n_base = n0 + warp_n * 32;
    #pragma unroll
    for (int mi = 0; mi < 2; mi++) {
        #pragma unroll
        for (int nj = 0; nj < 4; nj++) {
            const int col = n_base + nj * 8 + (lane & 3) * 2;
            const float bias0 = b1[col]   + (b2 ? b2[col]   : 0.f);
            const float bias1 = b1[col+1] + (b2 ? b2[col+1] : 0.f);
            #pragma unroll
            for (int half = 0; half < 2; half++) {
                const int row = m_base + mi * 16 + (lane >> 2) + half * 8;
                float v0 = acc[mi][nj][half*2 + 0] + bias0;
                float v1 = acc[mi][nj][half*2 + 1] + bias1;
                if (relu) { v0 = fmaxf(v0, 0.f); v1 = fmaxf(v1, 0.f); }
                if (C)
                    *reinterpret_cast<float2*>(C + (size_t)row * ldc + col) =
                        make_float2(v0, v1);
                if (Oh) {
                    bf16 h0 = __float2bfloat16(v0);
                    bf16 h1 = __float2bfloat16(v1);
                    bf16 l0 = __float2bfloat16(v0 - __bfloat162float(h0));
                    bf16 l1 = __float2bfloat16(v1 - __bfloat162float(h1));
                    bf16 hp[2] = {h0, h1}, lp[2] = {l0, l1};
                    *reinterpret_cast<uint32_t*>(Oh + (size_t)row * ldo + col) =
                        *reinterpret_cast<uint32_t*>(hp);
                    *reinterpret_cast<uint32_t*>(Ol + (size_t)row * ldo + col) =
                        *reinterpret_cast<uint32_t*>(lp);
                }
            }
        }
    }
}

// ---------------- fp32 GEMM (prologue only) ---------------------------------
template<int BM,int BN,int BK,int TM,int TN,int NT>
__global__ __launch_bounds__(NT)
void gemm2_kernel(const float* __restrict__ A1, int lda1,
                  const float* __restrict__ W1, int ldw1, int K1,
                  const float* __restrict__ A2, int lda2,
                  const float* __restrict__ W2, int ldw2, int K2,
                  const float* __restrict__ b1, const float* __restrict__ b2,
                  float* __restrict__ C, int ldc, int M, int N, int relu)
{
    __shared__ __align__(16) float As[BK][BM+4];
    __shared__ __align__(16) float Ws[BK][BN+4];
    const int tid = threadIdx.x;
    const int m0  = blockIdx.y * BM;
    const int n0  = blockIdx.x * BN;
    const int m0t = (tid / (BN/TN)) * TM;
    const int n0t = (tid % (BN/TN)) * TN;
    float acc[TM][TN];
    #pragma unroll
    for (int i = 0; i < TM; i++)
        #pragma unroll
        for (int j = 0; j < TN; j++) acc[i][j] = 0.f;
    for (int src = 0; src < 2; src++) {
        const float* A = src ? A2 : A1;
        if (A == nullptr) break;
        const float* W = src ? W2 : W1;
        const int lda = src ? lda2 : lda1;
        const int ldw = src ? ldw2 : ldw1;
        const int K   = src ? K2   : K1;
        for (int k0 = 0; k0 < K; k0 += BK) {
            constexpr int A4 = BM*BK/4;
            #pragma unroll
            for (int it = 0; it < A4/NT; it++) {
                int i4 = tid + NT*it;
                int row = i4 / (BK/4), cv = i4 % (BK/4);
                float4 val = make_float4(0,0,0,0);
                int gr = m0 + row;
                if (gr < M) val = *reinterpret_cast<const float4*>(A + (size_t)gr*lda + k0 + cv*4);
                As[cv*4+0][row]=val.x; As[cv*4+1][row]=val.y;
                As[cv*4+2][row]=val.z; As[cv*4+3][row]=val.w;
            }
            constexpr int W4 = BN*BK/4;
            #pragma unroll
            for (int it = 0; it < W4/NT; it++) {
                int i4 = tid + NT*it;
                int row = i4 / (BK/4), cv = i4 % (BK/4);
                float4 val = *reinterpret_cast<const float4*>(W + (size_t)(n0+row)*ldw + k0 + cv*4);
                Ws[cv*4+0][row]=val.x; Ws[cv*4+1][row]=val.y;
                Ws[cv*4+2][row]=val.z; Ws[cv*4+3][row]=val.w;
            }
            __syncthreads();
            #pragma unroll
            for (int kk = 0; kk < BK; kk++) {
                float a[TM], bb[TN];
                #pragma unroll
                for (int i = 0; i < TM; i += 4) {
                    float4 t = *reinterpret_cast<const float4*>(&As[kk][m0t+i]);
                    a[i]=t.x; a[i+1]=t.y; a[i+2]=t.z; a[i+3]=t.w;
                }
                #pragma unroll
                for (int j = 0; j < TN; j += 4) {
                    float4 t = *reinterpret_cast<const float4*>(&Ws[kk][n0t+j]);
                    bb[j]=t.x; bb[j+1]=t.y; bb[j+2]=t.z; bb[j+3]=t.w;
                }
                #pragma unroll
                for (int i = 0; i < TM; i++)
                    #pragma unroll
                    for (int j = 0; j < TN; j++)
                        acc[i][j] = fmaf(a[i], bb[j], acc[i][j]);
            }
            __syncthreads();
        }
    }
    #pragma unroll
    for (int j = 0; j < TN; j++) {
        int gn = n0 + n0t + j;
        float bias = (b1 ? b1[gn] : 0.f) + (b2 ? b2[gn] : 0.f);
        #pragma unroll
        for (int i = 0; i < TM; i++) {
            int gm = m0 + m0t + i;
            if (gm < M) {
                float vo = acc[i][j] + bias;
                if (relu) vo = fmaxf(vo, 0.f);
                C[(size_t)gm*ldc + gn] = vo;
            }
        }
    }
}

// ---------------- attention --------------------------------------------------
__global__ __launch_bounds__(256)
void attn_kernel(const float* __restrict__ q, const float* __restrict__ k,
                 const float* __restrict__ v, float* __restrict__ ctx)
{
    const int b = blockIdx.x, tid = threadIdx.x;
    const int lane = tid & 31, wid = tid >> 5;
    float p[S_];
    #pragma unroll
    for (int s = 0; s < S_; s++) p[s] = 0.f;
    for (int e = tid; e < H_; e += 256) {
        float qv = q[b*H_ + e];
        #pragma unroll
        for (int s = 0; s < S_; s++) p[s] = fmaf(qv, k[s*H_ + e], p[s]);
    }
    #pragma unroll
    for (int s = 0; s < S_; s++)
        #pragma unroll
        for (int off = 16; off > 0; off >>= 1)
            p[s] += __shfl_down_sync(0xffffffffu, p[s], off);
    __shared__ float sred[S_*8];
    __shared__ float wts[S_];
    if (lane == 0)
        #pragma unroll
        for (int s = 0; s < S_; s++) sred[s*8 + wid] = p[s];
    __syncthreads();
    if (tid == 0) {
        float sc[S_]; float mx = -1e30f;
        #pragma unroll
        for (int s = 0; s < S_; s++) {
            float a = 0.f;
            #pragma unroll
            for (int w = 0; w < 8; w++) a += sred[s*8 + w];
            sc[s] = a * (1.0f/32.0f);
            mx = fmaxf(mx, sc[s]);
        }
        float sum = 0.f;
        #pragma unroll
        for (int s = 0; s < S_; s++) { sc[s] = expf(sc[s]-mx); sum += sc[s]; }
        float inv = 1.f/sum;
        #pragma unroll
        for (int s = 0; s < S_; s++) wts[s] = sc[s]*inv;
    }
    __syncthreads();
    for (int j = tid; j < H_; j += 256) {
        float a = 0.f;
        #pragma unroll
        for (int s = 0; s < S_; s++) a = fmaf(wts[s], v[s*H_ + j], a);
        ctx[b*H_ + j] = a;
    }
}

// ---------------- pointwise LSTM cell (+ bf16 split of h) --------------------
__global__ __launch_bounds__(256)
void lstm_cell_kernel(const float* __restrict__ gates,
                      const float* __restrict__ c_in,
                      float* __restrict__ c_out,
                      bf16* __restrict__ hh, bf16* __restrict__ hl)
{
    int idx = blockIdx.x*blockDim.x + threadIdx.x;
    if (idx >= B_*H_) return;
    int b = idx >> 10, j = idx & (H_-1);
    const float* g = gates + (size_t)b*4*H_ + j;
    float gi = g[0], gf = g[H_], gg = g[2*H_], go = g[3*H_];
    float i  = 1.f / (1.f + expf(-gi));
    float f  = 1.f / (1.f + expf(-gf));
    float gt = tanhf(gg);
    float o  = 1.f / (1.f + expf(-go));
    float c  = f * c_in[idx] + i * gt;
    float h  = o * tanhf(c);
    c_out[idx] = c;
    bf16 hi = __float2bfloat16(h);
    hh[idx] = hi;
    hl[idx] = __float2bfloat16(h - __bfloat162float(hi));
}

// ---------------- split fp32 -> bf16 hi/lo -----------------------------------
__global__ __launch_bounds__(256)
void split_kernel(const float* __restrict__ src, bf16* __restrict__ hi,
                  bf16* __restrict__ lo, int n)
{
    int i = blockIdx.x*blockDim.x + threadIdx.x;
    if (i < n) {
        float v = src[i];
        bf16 h = __float2bfloat16(v);
        hi[i] = h;
        lo[i] = __float2bfloat16(v - __bfloat162float(h));
    }
}

// ---------------- zero state --------------------------------------------------
__global__ __launch_bounds__(256)
void zero_state_kernel()
{
    int i = blockIdx.x*blockDim.x + threadIdx.x;
    if (i < B_*H_) {
        g_c0[i] = 0.f; g_c1[i] = 0.f;
        bf16 z = __float2bfloat16(0.f);
        g_h0h[i] = z; g_h0l[i] = z; g_h1h[i] = z; g_h1l[i] = z;
    }
}

// ---------------- host helpers -------------------------------------------------
static inline void gemm_small(const float* A1,int lda1,const float* W1,int ldw1,int K1,
                              const float* A2,int lda2,const float* W2,int ldw2,int K2,
                              const float* b1,const float* b2,
                              float* C,int ldc,int M,int N,int relu)
{
    dim3 grid(N/32, (M + 63)/64);
    gemm2_kernel<64,32,16,4,4,128><<<grid,128>>>(A1,lda1,W1,ldw1,K1,
                                                 A2,lda2,W2,ldw2,K2,
                                                 b1,b2,C,ldc,M,N,relu);
}

static inline void launch_tc(const bf16* Ah1,const bf16* Al1,const bf16* Wh1,const bf16* Wl1,int K1,
                             const bf16* Ah2,const bf16* Al2,const bf16* Wh2,const bf16* Wl2,int K2,
                             const float* b1,const float* b2,
                             float* C,int ldc, bf16* Oh, bf16* Ol,int ldo,int N,int relu)
{
    dim3 grid(N/64, B_/128);
    gemm_mma<<<grid,256,MMA_SMEM>>>(Ah1,Al1,Wh1,Wl1,K1, Ah2,Al2,Wh2,Wl2,K2,
                                    b1,b2, C,ldc, Oh,Ol,ldo, relu);
}

extern "C" void kernel_launch(void* const* d_in, const int* in_sizes, int n_in,
                              void* d_out, int out_size)
{
    (void)in_sizes; (void)n_in;
    const float* cs   = (const float*)d_in[0];
    const float* mem  = (const float*)d_in[2];
    const float* qW   = (const float*)d_in[3];
    const float* qb   = (const float*)d_in[4];
    const float* kW   = (const float*)d_in[5];
    const float* kb   = (const float*)d_in[6];
    const float* vW   = (const float*)d_in[7];
    const float* vb   = (const float*)d_in[8];
    const float* moW  = (const float*)d_in[9];
    const float* mob  = (const float*)d_in[10];
    const float* pgW1 = (const float*)d_in[11];
    const float* pgb1 = (const float*)d_in[12];
    const float* pgW2 = (const float*)d_in[13];
    const float* pgb2 = (const float*)d_in[14];
    const float* wih0 = (const float*)d_in[15];
    const float* whh0 = (const float*)d_in[16];
    const float* bih0 = (const float*)d_in[17];
    const float* bhh0 = (const float*)d_in[18];
    const float* wih1 = (const float*)d_in[19];
    const float* whh1 = (const float*)d_in[20];
    const float* bih1 = (const float*)d_in[21];
    const float* bhh1 = (const float*)d_in[22];
    const float* opW1 = (const float*)d_in[23];
    const float* opb1 = (const float*)d_in[24];
    const float* opW2 = (const float*)d_in[25];
    const float* opb2 = (const float*)d_in[26];

    float* out = (float*)d_out;

    cudaFuncSetAttribute(gemm_mma, cudaFuncAttributeMaxDynamicSharedMemorySize, MMA_SMEM);

    // scratch addresses
    float *q,*km,*vm,*ctx,*cxt,*pgh,*prior_s,*gates,*c0,*c1;
    cudaGetSymbolAddress((void**)&q, g_q);
    cudaGetSymbolAddress((void**)&km, g_kmem);
    cudaGetSymbolAddress((void**)&vm, g_vmem);
    cudaGetSymbolAddress((void**)&ctx, g_ctx);
    cudaGetSymbolAddress((void**)&cxt, g_context);
    cudaGetSymbolAddress((void**)&pgh, g_pgh);
    cudaGetSymbolAddress((void**)&prior_s, g_prior);
    cudaGetSymbolAddress((void**)&gates, g_gates);
    cudaGetSymbolAddress((void**)&c0, g_c0);
    cudaGetSymbolAddress((void**)&c1, g_c1);

    bf16 *xh,*xl,*h0h,*h0l,*h1h,*h1l,*th,*tl;
    bf16 *wih0h,*wih0l,*whh0h,*whh0l,*wih1h,*wih1l,*whh1h,*whh1l,*oW1h,*oW1l,*oW2h,*oW2l;
    cudaGetSymbolAddress((void**)&xh, g_xh);   cudaGetSymbolAddress((void**)&xl, g_xl);
    cudaGetSymbolAddress((void**)&h0h, g_h0h); cudaGetSymbolAddress((void**)&h0l, g_h0l);
    cudaGetSymbolAddress((void**)&h1h, g_h1h); cudaGetSymbolAddress((void**)&h1l, g_h1l);
    cudaGetSymbolAddress((void**)&th, g_th);   cudaGetSymbolAddress((void**)&tl, g_tl);
    cudaGetSymbolAddress((void**)&wih0h, g_wih0h); cudaGetSymbolAddress((void**)&wih0l, g_wih0l);
    cudaGetSymbolAddress((void**)&whh0h, g_whh0h); cudaGetSymbolAddress((void**)&whh0l, g_whh0l);
    cudaGetSymbolAddress((void**)&wih1h, g_wih1h); cudaGetSymbolAddress((void**)&wih1l, g_wih1l);
    cudaGetSymbolAddress((void**)&whh1h, g_whh1h); cudaGetSymbolAddress((void**)&whh1l, g_whh1l);
    cudaGetSymbolAddress((void**)&oW1h, g_opW1h);  cudaGetSymbolAddress((void**)&oW1l, g_opW1l);
    cudaGetSymbolAddress((void**)&oW2h, g_opW2h);  cudaGetSymbolAddress((void**)&oW2l, g_opW2l);

    bool has_prior_region = (out_size >= PRED_ELEMS + B_*L_);
    float* priorbuf = has_prior_region ? (out + PRED_ELEMS) : prior_s;

    // ---- state init + weight conversion ----
    zero_state_kernel<<<(B_*H_ + 255)/256, 256>>>();
    split_kernel<<<(4*H_*L_ + 255)/256, 256>>>(wih0, wih0h, wih0l, 4*H_*L_);
    split_kernel<<<(4*H_*H_ + 255)/256, 256>>>(whh0, whh0h, whh0l, 4*H_*H_);
    split_kernel<<<(4*H_*H_ + 255)/256, 256>>>(wih1, wih1h, wih1l, 4*H_*H_);
    split_kernel<<<(4*H_*H_ + 255)/256, 256>>>(whh1, whh1h, whh1l, 4*H_*H_);
    split_kernel<<<(H_*H_ + 255)/256, 256>>>(opW1, oW1h, oW1l, H_*H_);
    split_kernel<<<(L_*H_ + 255)/256, 256>>>(opW2, oW2h, oW2l, L_*H_);

    // ---- prologue (fp32) ----
    gemm_small(cs, L_, qW, L_, L_,  nullptr,0,nullptr,0,0, qb,nullptr, q,  H_, B_, H_, 0);
    gemm_small(mem,H_, kW, H_, H_,  nullptr,0,nullptr,0,0, kb,nullptr, km, H_, S_, H_, 0);
    gemm_small(mem,H_, vW, H_, H_,  nullptr,0,nullptr,0,0, vb,nullptr, vm, H_, S_, H_, 0);
    attn_kernel<<<B_, 256>>>(q, km, vm, ctx);
    gemm_small(ctx,H_, moW,H_, H_,  nullptr,0,nullptr,0,0, mob,nullptr, cxt, L_, B_, L_, 0);
    gemm_small(cs, L_, pgW1,      2*L_, L_,
               cxt,L_, pgW1 + L_, 2*L_, L_,
               pgb1, nullptr, pgh, H_, B_, H_, 1);
    gemm_small(pgh,H_, pgW2,H_, H_, nullptr,0,nullptr,0,0, pgb2,nullptr,
               priorbuf, L_, B_, L_, 0);
    split_kernel<<<(B_*L_ + 255)/256, 256>>>(priorbuf, xh, xl, B_*L_);

    // ---- autoregressive rollout (tensor cores via mma.sync) ----
    for (int s = 0; s < HOR_; s++) {
        // layer 0 gates: x@wih0^T + h0@whh0^T
        launch_tc(xh, xl, wih0h, wih0l, L_,
                  h0h, h0l, whh0h, whh0l, H_,
                  bih0, bhh0, gates, 4*H_, nullptr, nullptr, 0, 4*H_, 0);
        lstm_cell_kernel<<<(B_*H_ + 255)/256, 256>>>(gates, c0, c0, h0h, h0l);

        // layer 1 gates: h0@wih1^T + h1@whh1^T
        launch_tc(h0h, h0l, wih1h, wih1l, H_,
                  h1h, h1l, whh1h, whh1l, H_,
                  bih1, bhh1, gates, 4*H_, nullptr, nullptr, 0, 4*H_, 0);
        lstm_cell_kernel<<<(B_*H_ + 255)/256, 256>>>(gates, c1, c1, h1h, h1l);

        // output proj: t = relu(h1@opW1^T + b1)  (bf16 split only)
        launch_tc(h1h, h1l, oW1h, oW1l, H_,
                  nullptr, nullptr, nullptr, nullptr, 0,
                  opb1, nullptr, nullptr, 0, th, tl, H_, H_, 1);
        // pred = t@opW2^T + b2 -> out (fp32) + split into x for next step
        launch_tc(th, tl, oW2h, oW2l, H_,
                  nullptr, nullptr, nullptr, nullptr, 0,
                  opb2, nullptr, out + (size_t)s*L_, HOR_*L_, xh, xl, L_, L_, 0);
    }
}

// round 6
// speedup vs baseline: 2.6503x; 1.1222x over previous
#include <cuda_runtime.h>
#include <cuda_bf16.h>
#include <math.h>
#include <stdint.h>

#define B_ 256
#define L_ 512
#define H_ 1024
#define S_ 16
#define HOR_ 64
#define PRED_ELEMS (B_*HOR_*L_)

typedef __nv_bfloat16 bf16;

// ---------------- fp32 scratch ----------------------------------------------
__device__ float g_q[B_*H_];
__device__ float g_kmem[S_*H_];
__device__ float g_vmem[S_*H_];
__device__ float g_ctx[B_*H_];
__device__ float g_context[B_*L_];
__device__ float g_pgh[B_*H_];
__device__ float g_prior[B_*L_];
__device__ float g_c0[B_*H_];
__device__ float g_c1[B_*H_];

// ---------------- bf16 split scratch ----------------------------------------
__device__ __align__(16) bf16 g_xh[B_*L_],  g_xl[B_*L_];
__device__ __align__(16) bf16 g_h0h[2][B_*H_], g_h0l[2][B_*H_];
__device__ __align__(16) bf16 g_h1h[2][B_*H_], g_h1l[2][B_*H_];
__device__ __align__(16) bf16 g_th[B_*H_],  g_tl[B_*H_];
__device__ __align__(16) bf16 g_wih0h[4*H_*L_], g_wih0l[4*H_*L_];
__device__ __align__(16) bf16 g_whh0h[4*H_*H_], g_whh0l[4*H_*H_];
__device__ __align__(16) bf16 g_wih1h[4*H_*H_], g_wih1l[4*H_*H_];
__device__ __align__(16) bf16 g_whh1h[4*H_*H_], g_whh1l[4*H_*H_];
__device__ __align__(16) bf16 g_opW1h[H_*H_],   g_opW1l[H_*H_];
__device__ __align__(16) bf16 g_opW2h[L_*H_],   g_opW2l[L_*H_];

// ---------------- low-level helpers ------------------------------------------
__device__ __forceinline__ uint32_t smem_u32(const void* p) {
    uint32_t a;
    asm("{ .reg .u64 t; cvta.to.shared.u64 t, %1; cvt.u32.u64 %0, t; }" : "=r"(a) : "l"(p));
    return a;
}

#define CP_ASYNC16(d, s) \
    asm volatile("cp.async.cg.shared.global [%0], [%1], 16;" :: "r"(d), "l"(s))
#define CP_COMMIT()  asm volatile("cp.async.commit_group;" ::: "memory")

__device__ __forceinline__ void ldm_x4(uint32_t* r, uint32_t addr) {
    asm volatile("ldmatrix.sync.aligned.m8n8.x4.shared.b16 {%0,%1,%2,%3}, [%4];"
                 : "=r"(r[0]), "=r"(r[1]), "=r"(r[2]), "=r"(r[3]) : "r"(addr));
}

__device__ __forceinline__ void mma16816(float* d, const uint32_t* a, const uint32_t* b) {
    asm volatile(
        "mma.sync.aligned.m16n8k16.row.col.f32.bf16.bf16.f32 "
        "{%0,%1,%2,%3}, {%4,%5,%6,%7}, {%8,%9}, {%0,%1,%2,%3};"
        : "+f"(d[0]), "+f"(d[1]), "+f"(d[2]), "+f"(d[3])
        : "r"(a[0]), "r"(a[1]), "r"(a[2]), "r"(a[3]), "r"(b[0]), "r"(b[1]));
}

// ---------------- tensor-core GEMM (bf16x3 split, fp32 accum, mma.sync) ------
// CTA tile 64x64, BK=32, 4 warps (warp 32x32), 3-stage cp.async pipeline.
// mode 0: standard epilogue (optional fp32 C, optional bf16 hi/lo out, relu)
// mode 1: fused LSTM cell. Weights are gate-interleaved (col n = 4*j + gate),
//         epilogue computes c_new/h and writes c + h(hi/lo) directly.
#define STRIDE 40                    // smem row stride (bf16 elems)
#define AH_OFF 0
#define AL_OFF (64*STRIDE)           // 2560
#define WH_OFF (2*64*STRIDE)         // 5120
#define WL_OFF (3*64*STRIDE)         // 7680
#define STAGE_ELEMS (4*64*STRIDE)    // 10240
#define STAGE_BYTES (STAGE_ELEMS*2)  // 20480
#define MMA_SMEM (3*STAGE_BYTES)     // 61440

__global__ __launch_bounds__(128)
void gemm_mma(const bf16* __restrict__ Ah1, const bf16* __restrict__ Al1,
              const bf16* __restrict__ Wh1, const bf16* __restrict__ Wl1, int K1,
              const bf16* __restrict__ Ah2, const bf16* __restrict__ Al2,
              const bf16* __restrict__ Wh2, const bf16* __restrict__ Wl2, int K2,
              const float* __restrict__ b1, const float* __restrict__ b2,
              float* __restrict__ C, int ldc,
              bf16* __restrict__ Oh, bf16* __restrict__ Ol, int ldo, int relu,
              int mode, const float* __restrict__ c_in, float* __restrict__ c_out)
{
    extern __shared__ __align__(16) char smem[];
    const uint32_t sb = smem_u32(smem);
    const int tid    = threadIdx.x;
    const int lane   = tid & 31;
    const int wid    = tid >> 5;
    const int warp_m = wid >> 1;          // 0..1
    const int warp_n = wid & 1;           // 0..1
    const int m0     = blockIdx.y * 64;
    const int n0     = blockIdx.x * 64;

    const int nc1 = K1 >> 5;
    const int nc2 = (Ah2 != nullptr) ? (K2 >> 5) : 0;
    const int nc  = nc1 + nc2;

    float acc[2][4][4];
    #pragma unroll
    for (int i = 0; i < 2; i++)
        #pragma unroll
        for (int j = 0; j < 4; j++)
            #pragma unroll
            for (int r = 0; r < 4; r++) acc[i][j][r] = 0.f;

    // ---- chunk loader: fill stage (c%3) with 32 K-columns of Ah/Al/Wh/Wl ----
    auto do_load = [&](int c) {
        const int  src = (c < nc1) ? 0 : 1;
        const int  k0  = ((src == 0) ? c : (c - nc1)) << 5;
        const int  K   = (src == 0) ? K1 : K2;
        const bf16* Ah = (src == 0) ? Ah1 : Ah2;
        const bf16* Al = (src == 0) ? Al1 : Al2;
        const bf16* Wh = (src == 0) ? Wh1 : Wh2;
        const bf16* Wl = (src == 0) ? Wl1 : Wl2;
        const uint32_t st = sb + (uint32_t)(c % 3) * STAGE_BYTES;

        #pragma unroll
        for (int it = 0; it < 2; it++) {       // 64 rows x 4 16B-chunks
            int idx = tid + (it << 7);
            int row = idx >> 2, ch = idx & 3;
            uint32_t doff = (uint32_t)(row * STRIDE + ch * 8) * 2u;
            const bf16* ga = Ah + (size_t)(m0 + row) * K + k0 + ch * 8;
            const bf16* gl = Al + (size_t)(m0 + row) * K + k0 + ch * 8;
            CP_ASYNC16(st + AH_OFF*2 + doff, ga);
            CP_ASYNC16(st + AL_OFF*2 + doff, gl);
            const bf16* gwh = Wh + (size_t)(n0 + row) * K + k0 + ch * 8;
            const bf16* gwl = Wl + (size_t)(n0 + row) * K + k0 + ch * 8;
            CP_ASYNC16(st + WH_OFF*2 + doff, gwh);
            CP_ASYNC16(st + WL_OFF*2 + doff, gwl);
        }
        CP_COMMIT();
    };

    do_load(0);
    do_load(1);

    // per-warp ldmatrix lane address components
    const int a_row = warp_m * 32 + (lane & 15);
    const int a_kof = (lane >> 4) << 3;
    const int b_row = warp_n * 32 + ((lane >> 4) << 3) + (lane & 7);
    const int b_kof = ((lane >> 3) & 1) << 3;

    for (int c = 0; c < nc; c++) {
        if (c == nc - 1) asm volatile("cp.async.wait_group 0;" ::: "memory");
        else             asm volatile("cp.async.wait_group 1;" ::: "memory");
        __syncthreads();

        if (c + 2 < nc) do_load(c + 2);     // write slot (c+2)%3, free since c-1

        const uint32_t st = sb + (uint32_t)(c % 3) * STAGE_BYTES;

        #pragma unroll
        for (int k16 = 0; k16 < 2; k16++) {
            const int kk = k16 * 16;
            uint32_t ah[2][4], al[2][4], bh[2][4], bl[2][4];
            #pragma unroll
            for (int mi = 0; mi < 2; mi++) {
                ldm_x4(ah[mi], st + (uint32_t)((AH_OFF + (a_row + mi*16) * STRIDE + kk + a_kof) * 2));
                ldm_x4(al[mi], st + (uint32_t)((AL_OFF + (a_row + mi*16) * STRIDE + kk + a_kof) * 2));
            }
            #pragma unroll
            for (int g = 0; g < 2; g++) {
                ldm_x4(bh[g], st + (uint32_t)((WH_OFF + (b_row + g*16) * STRIDE + kk + b_kof) * 2));
                ldm_x4(bl[g], st + (uint32_t)((WL_OFF + (b_row + g*16) * STRIDE + kk + b_kof) * 2));
            }
            #pragma unroll
            for (int mi = 0; mi < 2; mi++)
                #pragma unroll
                for (int nj = 0; nj < 4; nj++) {
                    const int g = nj >> 1, o = (nj & 1) * 2;
                    mma16816(acc[mi][nj], ah[mi], &bh[g][o]);
                    mma16816(acc[mi][nj], al[mi], &bh[g][o]);
                    mma16816(acc[mi][nj], ah[mi], &bl[g][o]);
                }
        }
        __syncthreads();
    }

    // ---------------- epilogue ----------------
    const int m_base = m0 + warp_m * 32;
    const int n_base = n0 + warp_n * 32;

    if (mode == 1) {
        // fused LSTM cell. col n = 4*j + gate; original bias row = gate*H + j.
        #pragma unroll
        for (int mi = 0; mi < 2; mi++) {
            #pragma unroll
            for (int nj = 0; nj < 4; nj++) {
                const int c0 = n_base + nj * 8 + (lane & 3) * 2;
                const int bi0 = (c0 & 3) * H_ + (c0 >> 2);
                const int bi1 = ((c0 + 1) & 3) * H_ + ((c0 + 1) >> 2);
                const float bias0 = b1[bi0] + b2[bi0];
                const float bias1 = b1[bi1] + b2[bi1];
                #pragma unroll
                for (int half = 0; half < 2; half++) {
                    const int row = m_base + mi * 16 + (lane >> 2) + half * 8;
                    float v0 = acc[mi][nj][half*2 + 0] + bias0;
                    float v1 = acc[mi][nj][half*2 + 1] + bias1;
                    float p0 = __shfl_xor_sync(0xffffffffu, v0, 1);
                    float p1 = __shfl_xor_sync(0xffffffffu, v1, 1);
                    if ((lane & 1) == 0) {
                        // this lane: (i,f); partner: (g,o)
                        const int j   = c0 >> 2;
                        const int idx = row * H_ + j;
                        float ig = 1.f / (1.f + expf(-v0));
                        float fg = 1.f / (1.f + expf(-v1));
                        float gg = tanhf(p0);
                        float og = 1.f / (1.f + expf(-p1));
                        float cv = fg * c_in[idx] + ig * gg;
                        float hv = og * tanhf(cv);
                        c_out[idx] = cv;
                        bf16 hb = __float2bfloat16(hv);
                        Oh[idx] = hb;
                        Ol[idx] = __float2bfloat16(hv - __bfloat162float(hb));
                    }
                }
            }
        }
    } else {
        #pragma unroll
        for (int mi = 0; mi < 2; mi++) {
            #pragma unroll
            for (int nj = 0; nj < 4; nj++) {
                const int col = n_base + nj * 8 + (lane & 3) * 2;
                const float bias0 = b1[col]   + (b2 ? b2[col]   : 0.f);
                const float bias1 = b1[col+1] + (b2 ? b2[col+1] : 0.f);
                #pragma unroll
                for (int half = 0; half < 2; half++) {
                    const int row = m_base + mi * 16 + (lane >> 2) + half * 8;
                    float v0 = acc[mi][nj][half*2 + 0] + bias0;
                    float v1 = acc[mi][nj][half*2 + 1] + bias1;
                    if (relu) { v0 = fmaxf(v0, 0.f); v1 = fmaxf(v1, 0.f); }
                    if (C)
                        *reinterpret_cast<float2*>(C + (size_t)row * ldc + col) =
                            make_float2(v0, v1);
                    if (Oh) {
                        bf16 h0 = __float2bfloat16(v0);
                        bf16 h1 = __float2bfloat16(v1);
                        bf16 l0 = __float2bfloat16(v0 - __bfloat162float(h0));
                        bf16 l1 = __float2bfloat16(v1 - __bfloat162float(h1));
                        bf16 hp[2] = {h0, h1}, lp[2] = {l0, l1};
                        *reinterpret_cast<uint32_t*>(Oh + (size_t)row * ldo + col) =
                            *reinterpret_cast<uint32_t*>(hp);
                        *reinterpret_cast<uint32_t*>(Ol + (size_t)row * ldo + col) =
                            *reinterpret_cast<uint32_t*>(lp);
                    }
                }
            }
        }
    }
}

// ---------------- fp32 GEMM (prologue only) ---------------------------------
template<int BM,int BN,int BK,int TM,int TN,int NT>
__global__ __launch_bounds__(NT)
void gemm2_kernel(const float* __restrict__ A1, int lda1,
                  const float* __restrict__ W1, int ldw1, int K1,
                  const float* __restrict__ A2, int lda2,
                  const float* __restrict__ W2, int ldw2, int K2,
                  const float* __restrict__ b1, const float* __restrict__ b2,
                  float* __restrict__ C, int ldc, int M, int N, int relu)
{
    __shared__ __align__(16) float As[BK][BM+4];
    __shared__ __align__(16) float Ws[BK][BN+4];
    const int tid = threadIdx.x;
    const int m0  = blockIdx.y * BM;
    const int n0  = blockIdx.x * BN;
    const int m0t = (tid / (BN/TN)) * TM;
    const int n0t = (tid % (BN/TN)) * TN;
    float acc[TM][TN];
    #pragma unroll
    for (int i = 0; i < TM; i++)
        #pragma unroll
        for (int j = 0; j < TN; j++) acc[i][j] = 0.f;
    for (int src = 0; src < 2; src++) {
        const float* A = src ? A2 : A1;
        if (A == nullptr) break;
        const float* W = src ? W2 : W1;
        const int lda = src ? lda2 : lda1;
        const int ldw = src ? ldw2 : ldw1;
        const int K   = src ? K2   : K1;
        for (int k0 = 0; k0 < K; k0 += BK) {
            constexpr int A4 = BM*BK/4;
            #pragma unroll
            for (int it = 0; it < A4/NT; it++) {
                int i4 = tid + NT*it;
                int row = i4 / (BK/4), cv = i4 % (BK/4);
                float4 val = make_float4(0,0,0,0);
                int gr = m0 + row;
                if (gr < M) val = *reinterpret_cast<const float4*>(A + (size_t)gr*lda + k0 + cv*4);
                As[cv*4+0][row]=val.x; As[cv*4+1][row]=val.y;
                As[cv*4+2][row]=val.z; As[cv*4+3][row]=val.w;
            }
            constexpr int W4 = BN*BK/4;
            #pragma unroll
            for (int it = 0; it < W4/NT; it++) {
                int i4 = tid + NT*it;
                int row = i4 / (BK/4), cv = i4 % (BK/4);
                float4 val = *reinterpret_cast<const float4*>(W + (size_t)(n0+row)*ldw + k0 + cv*4);
                Ws[cv*4+0][row]=val.x; Ws[cv*4+1][row]=val.y;
                Ws[cv*4+2][row]=val.z; Ws[cv*4+3][row]=val.w;
            }
            __syncthreads();
            #pragma unroll
            for (int kk = 0; kk < BK; kk++) {
                float a[TM], bb[TN];
                #pragma unroll
                for (int i = 0; i < TM; i += 4) {
                    float4 t = *reinterpret_cast<const float4*>(&As[kk][m0t+i]);
                    a[i]=t.x; a[i+1]=t.y; a[i+2]=t.z; a[i+3]=t.w;
                }
                #pragma unroll
                for (int j = 0; j < TN; j += 4) {
                    float4 t = *reinterpret_cast<const float4*>(&Ws[kk][n0t+j]);
                    bb[j]=t.x; bb[j+1]=t.y; bb[j+2]=t.z; bb[j+3]=t.w;
                }
                #pragma unroll
                for (int i = 0; i < TM; i++)
                    #pragma unroll
                    for (int j = 0; j < TN; j++)
                        acc[i][j] = fmaf(a[i], bb[j], acc[i][j]);
            }
            __syncthreads();
        }
    }
    #pragma unroll
    for (int j = 0; j < TN; j++) {
        int gn = n0 + n0t + j;
        float bias = (b1 ? b1[gn] : 0.f) + (b2 ? b2[gn] : 0.f);
        #pragma unroll
        for (int i = 0; i < TM; i++) {
            int gm = m0 + m0t + i;
            if (gm < M) {
                float vo = acc[i][j] + bias;
                if (relu) vo = fmaxf(vo, 0.f);
                C[(size_t)gm*ldc + gn] = vo;
            }
        }
    }
}

// ---------------- attention --------------------------------------------------
__global__ __launch_bounds__(256)
void attn_kernel(const float* __restrict__ q, const float* __restrict__ k,
                 const float* __restrict__ v, float* __restrict__ ctx)
{
    const int b = blockIdx.x, tid = threadIdx.x;
    const int lane = tid & 31, wid = tid >> 5;
    float p[S_];
    #pragma unroll
    for (int s = 0; s < S_; s++) p[s] = 0.f;
    for (int e = tid; e < H_; e += 256) {
        float qv = q[b*H_ + e];
        #pragma unroll
        for (int s = 0; s < S_; s++) p[s] = fmaf(qv, k[s*H_ + e], p[s]);
    }
    #pragma unroll
    for (int s = 0; s < S_; s++)
        #pragma unroll
        for (int off = 16; off > 0; off >>= 1)
            p[s] += __shfl_down_sync(0xffffffffu, p[s], off);
    __shared__ float sred[S_*8];
    __shared__ float wts[S_];
    if (lane == 0)
        #pragma unroll
        for (int s = 0; s < S_; s++) sred[s*8 + wid] = p[s];
    __syncthreads();
    if (tid == 0) {
        float sc[S_]; float mx = -1e30f;
        #pragma unroll
        for (int s = 0; s < S_; s++) {
            float a = 0.f;
            #pragma unroll
            for (int w = 0; w < 8; w++) a += sred[s*8 + w];
            sc[s] = a * (1.0f/32.0f);
            mx = fmaxf(mx, sc[s]);
        }
        float sum = 0.f;
        #pragma unroll
        for (int s = 0; s < S_; s++) { sc[s] = expf(sc[s]-mx); sum += sc[s]; }
        float inv = 1.f/sum;
        #pragma unroll
        for (int s = 0; s < S_; s++) wts[s] = sc[s]*inv;
    }
    __syncthreads();
    for (int j = tid; j < H_; j += 256) {
        float a = 0.f;
        #pragma unroll
        for (int s = 0; s < S_; s++) a = fmaf(wts[s], v[s*H_ + j], a);
        ctx[b*H_ + j] = a;
    }
}

// ---------------- splits ------------------------------------------------------
__global__ __launch_bounds__(256)
void split_kernel(const float* __restrict__ src, bf16* __restrict__ hi,
                  bf16* __restrict__ lo, int n)
{
    int i = blockIdx.x*blockDim.x + threadIdx.x;
    if (i < n) {
        float v = src[i];
        bf16 h = __float2bfloat16(v);
        hi[i] = h;
        lo[i] = __float2bfloat16(v - __bfloat162float(h));
    }
}

// gate-interleaving split: out row n = 4*j + g  <-  in row g*H + j   (in: [4H, K])
__global__ __launch_bounds__(256)
void split_gate_kernel(const float* __restrict__ src, bf16* __restrict__ hi,
                       bf16* __restrict__ lo, int K, int n)
{
    int i = blockIdx.x*blockDim.x + threadIdx.x;
    if (i < n) {
        int row = i / K, k = i - row * K;
        int orow = (row & 3) * H_ + (row >> 2);
        float v = src[(size_t)orow * K + k];
        bf16 h = __float2bfloat16(v);
        hi[i] = h;
        lo[i] = __float2bfloat16(v - __bfloat162float(h));
    }
}

__global__ __launch_bounds__(256)
void zero_state_kernel()
{
    int i = blockIdx.x*blockDim.x + threadIdx.x;
    if (i < B_*H_) {
        g_c0[i] = 0.f; g_c1[i] = 0.f;
        bf16 z = __float2bfloat16(0.f);
        g_h0h[0][i] = z; g_h0l[0][i] = z; g_h1h[0][i] = z; g_h1l[0][i] = z;
        g_h0h[1][i] = z; g_h0l[1][i] = z; g_h1h[1][i] = z; g_h1l[1][i] = z;
    }
}

// ---------------- host helpers -------------------------------------------------
static inline void gemm_small(const float* A1,int lda1,const float* W1,int ldw1,int K1,
                              const float* A2,int lda2,const float* W2,int ldw2,int K2,
                              const float* b1,const float* b2,
                              float* C,int ldc,int M,int N,int relu)
{
    dim3 grid(N/32, (M + 63)/64);
    gemm2_kernel<64,32,16,4,4,128><<<grid,128>>>(A1,lda1,W1,ldw1,K1,
                                                 A2,lda2,W2,ldw2,K2,
                                                 b1,b2,C,ldc,M,N,relu);
}

static inline void launch_gates(const bf16* Ah1,const bf16* Al1,const bf16* Wh1,const bf16* Wl1,int K1,
                                const bf16* Ah2,const bf16* Al2,const bf16* Wh2,const bf16* Wl2,int K2,
                                const float* b1,const float* b2,
                                const float* cin, float* cout, bf16* hh, bf16* hl)
{
    dim3 grid(4*H_/64, B_/64);   // (64, 4)
    gemm_mma<<<grid,128,MMA_SMEM>>>(Ah1,Al1,Wh1,Wl1,K1, Ah2,Al2,Wh2,Wl2,K2,
                                    b1,b2, nullptr,0, hh,hl,0, 0, 1, cin, cout);
}

static inline void launch_std(const bf16* Ah1,const bf16* Al1,const bf16* Wh1,const bf16* Wl1,int K1,
                              const float* b1,
                              float* C,int ldc, bf16* Oh, bf16* Ol,int ldo,int N,int relu)
{
    dim3 grid(N/64, B_/64);
    gemm_mma<<<grid,128,MMA_SMEM>>>(Ah1,Al1,Wh1,Wl1,K1,
                                    nullptr,nullptr,nullptr,nullptr,0,
                                    b1,nullptr, C,ldc, Oh,Ol,ldo, relu, 0, nullptr, nullptr);
}

extern "C" void kernel_launch(void* const* d_in, const int* in_sizes, int n_in,
                              void* d_out, int out_size)
{
    (void)in_sizes; (void)n_in;
    const float* cs   = (const float*)d_in[0];
    const float* mem  = (const float*)d_in[2];
    const float* qW   = (const float*)d_in[3];
    const float* qb   = (const float*)d_in[4];
    const float* kW   = (const float*)d_in[5];
    const float* kb   = (const float*)d_in[6];
    const float* vW   = (const float*)d_in[7];
    const float* vb   = (const float*)d_in[8];
    const float* moW  = (const float*)d_in[9];
    const float* mob  = (const float*)d_in[10];
    const float* pgW1 = (const float*)d_in[11];
    const float* pgb1 = (const float*)d_in[12];
    const float* pgW2 = (const float*)d_in[13];
    const float* pgb2 = (const float*)d_in[14];
    const float* wih0 = (const float*)d_in[15];
    const float* whh0 = (const float*)d_in[16];
    const float* bih0 = (const float*)d_in[17];
    const float* bhh0 = (const float*)d_in[18];
    const float* wih1 = (const float*)d_in[19];
    const float* whh1 = (const float*)d_in[20];
    const float* bih1 = (const float*)d_in[21];
    const float* bhh1 = (const float*)d_in[22];
    const float* opW1 = (const float*)d_in[23];
    const float* opb1 = (const float*)d_in[24];
    const float* opW2 = (const float*)d_in[25];
    const float* opb2 = (const float*)d_in[26];

    float* out = (float*)d_out;

    cudaFuncSetAttribute(gemm_mma, cudaFuncAttributeMaxDynamicSharedMemorySize, MMA_SMEM);

    // scratch addresses
    float *q,*km,*vm,*ctx,*cxt,*pgh,*prior_s,*c0,*c1;
    cudaGetSymbolAddress((void**)&q, g_q);
    cudaGetSymbolAddress((void**)&km, g_kmem);
    cudaGetSymbolAddress((void**)&vm, g_vmem);
    cudaGetSymbolAddress((void**)&ctx, g_ctx);
    cudaGetSymbolAddress((void**)&cxt, g_context);
    cudaGetSymbolAddress((void**)&pgh, g_pgh);
    cudaGetSymbolAddress((void**)&prior_s, g_prior);
    cudaGetSymbolAddress((void**)&c0, g_c0);
    cudaGetSymbolAddress((void**)&c1, g_c1);

    bf16 *xh,*xl,*h0h,*h0l,*h1h,*h1l,*th,*tl;
    bf16 *wih0h,*wih0l,*whh0h,*whh0l,*wih1h,*wih1l,*whh1h,*whh1l,*oW1h,*oW1l,*oW2h,*oW2l;
    cudaGetSymbolAddress((void**)&xh, g_xh);   cudaGetSymbolAddress((void**)&xl, g_xl);
    cudaGetSymbolAddress((void**)&h0h, g_h0h); cudaGetSymbolAddress((void**)&h0l, g_h0l);
    cudaGetSymbolAddress((void**)&h1h, g_h1h); cudaGetSymbolAddress((void**)&h1l, g_h1l);
    cudaGetSymbolAddress((void**)&th, g_th);   cudaGetSymbolAddress((void**)&tl, g_tl);
    cudaGetSymbolAddress((void**)&wih0h, g_wih0h); cudaGetSymbolAddress((void**)&wih0l, g_wih0l);
    cudaGetSymbolAddress((void**)&whh0h, g_whh0h); cudaGetSymbolAddress((void**)&whh0l, g_whh0l);
    cudaGetSymbolAddress((void**)&wih1h, g_wih1h); cudaGetSymbolAddress((void**)&wih1l, g_wih1l);
    cudaGetSymbolAddress((void**)&whh1h, g_whh1h); cudaGetSymbolAddress((void**)&whh1l, g_whh1l);
    cudaGetSymbolAddress((void**)&oW1h, g_opW1h);  cudaGetSymbolAddress((void**)&oW1l, g_opW1l);
    cudaGetSymbolAddress((void**)&oW2h, g_opW2h);  cudaGetSymbolAddress((void**)&oW2l, g_opW2l);

    bool has_prior_region = (out_size >= PRED_ELEMS + B_*L_);
    float* priorbuf = has_prior_region ? (out + PRED_ELEMS) : prior_s;

    // ---- state init + weight conversion (gate weights permuted to 4j+g order)
    zero_state_kernel<<<(B_*H_ + 255)/256, 256>>>();
    split_gate_kernel<<<(4*H_*L_ + 255)/256, 256>>>(wih0, wih0h, wih0l, L_, 4*H_*L_);
    split_gate_kernel<<<(4*H_*H_ + 255)/256, 256>>>(whh0, whh0h, whh0l, H_, 4*H_*H_);
    split_gate_kernel<<<(4*H_*H_ + 255)/256, 256>>>(wih1, wih1h, wih1l, H_, 4*H_*H_);
    split_gate_kernel<<<(4*H_*H_ + 255)/256, 256>>>(whh1, whh1h, whh1l, H_, 4*H_*H_);
    split_kernel<<<(H_*H_ + 255)/256, 256>>>(opW1, oW1h, oW1l, H_*H_);
    split_kernel<<<(L_*H_ + 255)/256, 256>>>(opW2, oW2h, oW2l, L_*H_);

    // ---- prologue (fp32) ----
    gemm_small(cs, L_, qW, L_, L_,  nullptr,0,nullptr,0,0, qb,nullptr, q,  H_, B_, H_, 0);
    gemm_small(mem,H_, kW, H_, H_,  nullptr,0,nullptr,0,0, kb,nullptr, km, H_, S_, H_, 0);
    gemm_small(mem,H_, vW, H_, H_,  nullptr,0,nullptr,0,0, vb,nullptr, vm, H_, S_, H_, 0);
    attn_kernel<<<B_, 256>>>(q, km, vm, ctx);
    gemm_small(ctx,H_, moW,H_, H_,  nullptr,0,nullptr,0,0, mob,nullptr, cxt, L_, B_, L_, 0);
    gemm_small(cs, L_, pgW1,      2*L_, L_,
               cxt,L_, pgW1 + L_, 2*L_, L_,
               pgb1, nullptr, pgh, H_, B_, H_, 1);
    gemm_small(pgh,H_, pgW2,H_, H_, nullptr,0,nullptr,0,0, pgb2,nullptr,
               priorbuf, L_, B_, L_, 0);
    split_kernel<<<(B_*L_ + 255)/256, 256>>>(priorbuf, xh, xl, B_*L_);

    // ---- autoregressive rollout: 4 kernels/step, cell fused into gate GEMMs --
    for (int s = 0; s < HOR_; s++) {
        const int p  = s & 1;
        const int pn = p ^ 1;
        // layer 0: gates + cell -> h0[pn], c0
        launch_gates(xh, xl, wih0h, wih0l, L_,
                     h0h + (size_t)p*B_*H_, h0l + (size_t)p*B_*H_, whh0h, whh0l, H_,
                     bih0, bhh0, c0, c0,
                     h0h + (size_t)pn*B_*H_, h0l + (size_t)pn*B_*H_);
        // layer 1: gates + cell -> h1[pn], c1
        launch_gates(h0h + (size_t)pn*B_*H_, h0l + (size_t)pn*B_*H_, wih1h, wih1l, H_,
                     h1h + (size_t)p*B_*H_, h1l + (size_t)p*B_*H_, whh1h, whh1l, H_,
                     bih1, bhh1, c1, c1,
                     h1h + (size_t)pn*B_*H_, h1l + (size_t)pn*B_*H_);
        // op1: t = relu(h1 @ opW1^T + b1)
        launch_std(h1h + (size_t)pn*B_*H_, h1l + (size_t)pn*B_*H_, oW1h, oW1l, H_,
                   opb1, nullptr, 0, th, tl, H_, H_, 1);
        // op2: pred -> out, and split into x for next step
        launch_std(th, tl, oW2h, oW2l, H_,
                   opb2, out + (size_t)s*L_, HOR_*L_, xh, xl, L_, L_, 0);
    }
}